// round 5
// baseline (speedup 1.0000x reference)
#include <cuda_runtime.h>
#include <stdint.h>

// Problem dims
#define T_ 4
#define B_ 32
#define C_ 512
#define N_ 196            // H*W = 14*14
#define TB_ 128           // T*B
#define BCN_ 3211264      // B*C*N
#define TBCN_ 12845056    // T*B*C*N
#define J_ 25088          // TB*N  (GEMM columns)

// ---------------- static scratch (allocation-free) ----------------
__device__ unsigned char g_xs[TBCN_];   // x spikes, [tb, c, n]
__device__ float g_qp[TBCN_];           // q pre-act (post-BN), [c, j] (j = tb*196+n)
__device__ float g_kp[TBCN_];
__device__ float g_vp[TBCN_];
__device__ unsigned char g_qs[TBCN_];   // spikes [tb, c, n]
__device__ unsigned char g_ks[TBCN_];
__device__ unsigned char g_vs[TBCN_];
__device__ unsigned char g_kvs[TB_ * C_];  // kv spikes [tb, c]

// ---------------- K1: shortcut LIF on x ----------------
__global__ void lif_x_kernel(const float* __restrict__ x, unsigned char* __restrict__ xs) {
    int i = blockIdx.x * blockDim.x + threadIdx.x;
    if (i >= BCN_) return;
    float v = 0.f;
#pragma unroll
    for (int t = 0; t < T_; t++) {
        float xv = x[t * BCN_ + i];
        v = v + (xv - v) * 0.5f;
        bool s = (v >= 1.0f);
        xs[t * BCN_ + i] = (unsigned char)s;
        if (s) v = 0.f;
    }
}

// ---------------- K2: fused Q/K/V GEMM + BN ----------------
struct QKVParams {
    const float* W[3];
    const float* g[3];
    const float* bb[3];
    const float* m[3];
    const float* vv[3];
    float* out[3];
};

#define BM 64
#define BJ 64
#define BK 32

__global__ __launch_bounds__(256) void gemm_qkv_kernel(const unsigned char* __restrict__ xs,
                                                       QKVParams p) {
    int z = blockIdx.z;
    const float* __restrict__ W = p.W[z];
    __shared__ float Ws[BK][BM + 4];
    __shared__ float Xs[BK][BJ + 4];

    int d0 = blockIdx.y * BM;
    int j0 = blockIdx.x * BJ;
    int tid = threadIdx.x;
    int tx = tid & 15, ty = tid >> 4;

    float acc[4][4];
#pragma unroll
    for (int a = 0; a < 4; a++)
#pragma unroll
        for (int b = 0; b < 4; b++) acc[a][b] = 0.f;

    for (int c0 = 0; c0 < C_; c0 += BK) {
#pragma unroll
        for (int i = 0; i < 8; i++) {
            int e = tid + i * 256;
            int r = e >> 5, cc = e & 31;
            Ws[cc][r] = W[(d0 + r) * C_ + c0 + cc];
        }
#pragma unroll
        for (int i = 0; i < 8; i++) {
            int e = tid + i * 256;
            int cc = e >> 6, jj = e & 63;
            int j = j0 + jj;
            int tb = j / N_;
            int n = j - tb * N_;
            Xs[cc][jj] = (float)xs[(tb * C_ + c0 + cc) * N_ + n];
        }
        __syncthreads();
#pragma unroll
        for (int k = 0; k < BK; k++) {
            float a[4], b[4];
            *(float4*)a = *(const float4*)&Ws[k][ty * 4];
            *(float4*)b = *(const float4*)&Xs[k][tx * 4];
#pragma unroll
            for (int di = 0; di < 4; di++)
#pragma unroll
                for (int ji = 0; ji < 4; ji++) acc[di][ji] += a[di] * b[ji];
        }
        __syncthreads();
    }

    const float* gg = p.g[z];
    const float* gb = p.bb[z];
    const float* gm = p.m[z];
    const float* gv = p.vv[z];
    float* O = p.out[z];
#pragma unroll
    for (int di = 0; di < 4; di++) {
        int d = d0 + ty * 4 + di;
        float sc = gg[d] / sqrtf(gv[d] + 1e-5f);
        float sh = gb[d] - gm[d] * sc;
#pragma unroll
        for (int ji = 0; ji < 4; ji++) {
            int j = j0 + tx * 4 + ji;
            O[d * J_ + j] = acc[di][ji] * sc + sh;
        }
    }
}

// ---------------- K3: LIF on q/k/v pre-activations ----------------
// pre layout [c, j]; spikes layout [tb, c, n]; optionally write vh (head layout) to d_out.
__global__ void lif_qkv_kernel(const float* __restrict__ pre, unsigned char* __restrict__ sp,
                               float* __restrict__ vh /* may be null */) {
    int i = blockIdx.x * blockDim.x + threadIdx.x;
    if (i >= BCN_) return;
    int c = i / (B_ * N_);
    int r = i - c * (B_ * N_);
    int b = r / N_;
    int n = r - b * N_;
    float v = 0.f;
#pragma unroll
    for (int t = 0; t < T_; t++) {
        int tb = t * B_ + b;
        float pv = pre[c * J_ + tb * N_ + n];
        v = v + (pv - v) * 0.5f;
        bool s = (v >= 1.0f);
        sp[(tb * C_ + c) * N_ + n] = (unsigned char)s;
        if (vh) {
            int h = c >> 6, dd = c & 63;
            vh[(((tb * 8) + h) * N_ + n) * 64 + dd] = s ? 1.0f : 0.0f;
        }
        if (s) v = 0.f;
    }
}

// ---------------- K4: kv = sum_n(k*v), then LIF over t ----------------
__global__ void kv_lif_kernel(const unsigned char* __restrict__ ks,
                              const unsigned char* __restrict__ vs,
                              unsigned char* __restrict__ kvs) {
    __shared__ unsigned int sk[6272];  // 128 rows * 196 bytes / 4
    __shared__ unsigned int sv[6272];
    int b = blockIdx.x >> 2;
    int c0 = (blockIdx.x & 3) * 128;
    int tid = threadIdx.x;  // 128 threads, one per channel in tile
    float vst = 0.f;
    for (int t = 0; t < T_; t++) {
        int base = ((t * B_ + b) * C_ + c0) * N_;  // byte offset, 4-aligned (196%4==0)
        const unsigned int* gk = (const unsigned int*)(ks + base);
        const unsigned int* gv = (const unsigned int*)(vs + base);
        for (int i = tid; i < 6272; i += 128) { sk[i] = gk[i]; sv[i] = gv[i]; }
        __syncthreads();
        const unsigned char* rk = ((const unsigned char*)sk) + tid * N_;
        const unsigned char* rv = ((const unsigned char*)sv) + tid * N_;
        int cnt = 0;
#pragma unroll 4
        for (int n = 0; n < N_; n++) cnt += (int)(rk[n] & rv[n]);
        float pre = (float)cnt;           // exact integer
        vst = vst + (pre - vst) * 0.5f;   // exact dyadic arithmetic
        bool s = (vst >= 1.0f);
        kvs[(t * B_ + b) * C_ + c0 + tid] = (unsigned char)s;
        if (s) vst = 0.f;
        __syncthreads();
    }
}

// ---------------- K5: out GEMM (y = q_s & kv_s) + bias + BN + residual ----------------
__global__ __launch_bounds__(256) void gemm_out_kernel(const unsigned char* __restrict__ qs,
                                                       const unsigned char* __restrict__ kvs,
                                                       const float* __restrict__ W,
                                                       const float* __restrict__ bias,
                                                       const float* __restrict__ gg,
                                                       const float* __restrict__ gb,
                                                       const float* __restrict__ gm,
                                                       const float* __restrict__ gv,
                                                       const float* __restrict__ xid,
                                                       float* __restrict__ out) {
    __shared__ float Ws[BK][BM + 4];
    __shared__ float Xs[BK][BJ + 4];

    int d0 = blockIdx.y * BM;
    int j0 = blockIdx.x * BJ;
    int tid = threadIdx.x;
    int tx = tid & 15, ty = tid >> 4;

    float acc[4][4];
#pragma unroll
    for (int a = 0; a < 4; a++)
#pragma unroll
        for (int b = 0; b < 4; b++) acc[a][b] = 0.f;

    for (int c0 = 0; c0 < C_; c0 += BK) {
#pragma unroll
        for (int i = 0; i < 8; i++) {
            int e = tid + i * 256;
            int r = e >> 5, cc = e & 31;
            Ws[cc][r] = W[(d0 + r) * C_ + c0 + cc];
        }
#pragma unroll
        for (int i = 0; i < 8; i++) {
            int e = tid + i * 256;
            int cc = e >> 6, jj = e & 63;
            int j = j0 + jj;
            int tb = j / N_;
            int n = j - tb * N_;
            int c = c0 + cc;
            unsigned char y = qs[(tb * C_ + c) * N_ + n] & kvs[tb * C_ + c];
            Xs[cc][jj] = (float)y;
        }
        __syncthreads();
#pragma unroll
        for (int k = 0; k < BK; k++) {
            float a[4], b[4];
            *(float4*)a = *(const float4*)&Ws[k][ty * 4];
            *(float4*)b = *(const float4*)&Xs[k][tx * 4];
#pragma unroll
            for (int di = 0; di < 4; di++)
#pragma unroll
                for (int ji = 0; ji < 4; ji++) acc[di][ji] += a[di] * b[ji];
        }
        __syncthreads();
    }

#pragma unroll
    for (int di = 0; di < 4; di++) {
        int d = d0 + ty * 4 + di;
        float sc = gg[d] / sqrtf(gv[d] + 1e-5f);
        float sh = gb[d] - gm[d] * sc;
        float bs = bias[d];
#pragma unroll
        for (int ji = 0; ji < 4; ji++) {
            int j = j0 + tx * 4 + ji;
            int tb = j / N_;
            int n = j - tb * N_;
            int gi = (tb * C_ + d) * N_ + n;
            float val = (acc[di][ji] + bs) * sc + sh + xid[gi];
            out[gi] = val;
        }
    }
}

// ---------------- host launch ----------------
extern "C" void kernel_launch(void* const* d_in, const int* in_sizes, int n_in,
                              void* d_out, int out_size) {
    // Detect input ordering: weights are 262144 elements.
    const float *x, *qw, *kw, *vw, *ow, *ob;
    const float *qg, *qb, *qm, *qv, *kg, *kb, *km, *kvv, *vg, *vb, *vm, *vvv, *og, *obb, *om, *ov;
    if (n_in >= 5 && in_sizes[2] == 262144) {
        // dict order: x, q_w, k_w, v_w, out_w, out_b, then q/k/v/out bn (g,b,m,v)
        x = (const float*)d_in[0];
        qw = (const float*)d_in[1];
        kw = (const float*)d_in[2];
        vw = (const float*)d_in[3];
        ow = (const float*)d_in[4];
        ob = (const float*)d_in[5];
        qg = (const float*)d_in[6];  qb = (const float*)d_in[7];  qm = (const float*)d_in[8];  qv = (const float*)d_in[9];
        kg = (const float*)d_in[10]; kb = (const float*)d_in[11]; km = (const float*)d_in[12]; kvv = (const float*)d_in[13];
        vg = (const float*)d_in[14]; vb = (const float*)d_in[15]; vm = (const float*)d_in[16]; vvv = (const float*)d_in[17];
        og = (const float*)d_in[18]; obb = (const float*)d_in[19]; om = (const float*)d_in[20]; ov = (const float*)d_in[21];
    } else {
        // signature order
        x = (const float*)d_in[0];
        qw = (const float*)d_in[1];
        qg = (const float*)d_in[2];  qb = (const float*)d_in[3];  qm = (const float*)d_in[4];  qv = (const float*)d_in[5];
        kw = (const float*)d_in[6];
        kg = (const float*)d_in[7];  kb = (const float*)d_in[8];  km = (const float*)d_in[9];  kvv = (const float*)d_in[10];
        vw = (const float*)d_in[11];
        vg = (const float*)d_in[12]; vb = (const float*)d_in[13]; vm = (const float*)d_in[14]; vvv = (const float*)d_in[15];
        ow = (const float*)d_in[16];
        ob = (const float*)d_in[17];
        og = (const float*)d_in[18]; obb = (const float*)d_in[19]; om = (const float*)d_in[20]; ov = (const float*)d_in[21];
    }

    float* out1 = (float*)d_out;                 // y + identity, [T,B,C,H,W]
    float* out2 = (float*)d_out + TBCN_;         // vh, [T,B,heads,N,hd]

    unsigned char *xs, *qs, *ks, *vs, *kvs;
    float *qp, *kp, *vp;
    cudaGetSymbolAddress((void**)&xs, g_xs);
    cudaGetSymbolAddress((void**)&qs, g_qs);
    cudaGetSymbolAddress((void**)&ks, g_ks);
    cudaGetSymbolAddress((void**)&vs, g_vs);
    cudaGetSymbolAddress((void**)&kvs, g_kvs);
    cudaGetSymbolAddress((void**)&qp, g_qp);
    cudaGetSymbolAddress((void**)&kp, g_kp);
    cudaGetSymbolAddress((void**)&vp, g_vp);

    // K1: shortcut LIF
    lif_x_kernel<<<(BCN_ + 255) / 256, 256>>>(x, xs);

    // K2: fused q/k/v GEMM + BN
    QKVParams p;
    p.W[0] = qw; p.W[1] = kw; p.W[2] = vw;
    p.g[0] = qg; p.g[1] = kg; p.g[2] = vg;
    p.bb[0] = qb; p.bb[1] = kb; p.bb[2] = vb;
    p.m[0] = qm; p.m[1] = km; p.m[2] = vm;
    p.vv[0] = qv; p.vv[1] = kvv; p.vv[2] = vvv;
    p.out[0] = qp; p.out[1] = kp; p.out[2] = vp;
    dim3 g2(J_ / BJ, C_ / BM, 3);
    gemm_qkv_kernel<<<g2, 256>>>(xs, p);

    // K3: LIF on q, k, v (v also emits vh output)
    lif_qkv_kernel<<<(BCN_ + 255) / 256, 256>>>(qp, qs, nullptr);
    lif_qkv_kernel<<<(BCN_ + 255) / 256, 256>>>(kp, ks, nullptr);
    lif_qkv_kernel<<<(BCN_ + 255) / 256, 256>>>(vp, vs, out2);

    // K4: kv reduction + LIF
    kv_lif_kernel<<<B_ * 4, 128>>>(ks, vs, kvs);

    // K5: out GEMM + bias + BN + residual
    dim3 g5(J_ / BJ, C_ / BM, 1);
    gemm_out_kernel<<<g5, 256>>>(qs, kvs, ow, ob, og, obb, om, ov, x, out1);
}

// round 6
// speedup vs baseline: 1.0039x; 1.0039x over previous
#include <cuda_runtime.h>
#include <stdint.h>

// Problem dims
#define T_ 4
#define B_ 32
#define C_ 512
#define N_ 196            // H*W = 14*14
#define TB_ 128           // T*B
#define BCN_ 3211264      // B*C*N
#define TBCN_ 12845056    // T*B*C*N
#define J_ 25088          // TB*N  (GEMM columns)

// ---------------- static scratch (allocation-free) ----------------
__device__ unsigned char g_xs[TBCN_];   // x spikes, [tb, c, n]
__device__ float g_qp[TBCN_];           // q pre-act (post-BN), [c, j] (j = tb*196+n)
__device__ float g_kp[TBCN_];
__device__ float g_vp[TBCN_];
__device__ unsigned char g_qs[TBCN_];   // spikes [tb, c, n]
__device__ unsigned char g_ks[TBCN_];
__device__ unsigned char g_vs[TBCN_];
__device__ unsigned char g_kvs[TB_ * C_];  // kv spikes [tb, c]

// ---------------- K1: shortcut LIF on x ----------------
__global__ void lif_x_kernel(const float* __restrict__ x, unsigned char* __restrict__ xs) {
    int i = blockIdx.x * blockDim.x + threadIdx.x;
    if (i >= BCN_) return;
    float v = 0.f;
#pragma unroll
    for (int t = 0; t < T_; t++) {
        float xv = x[t * BCN_ + i];
        v = v + (xv - v) * 0.5f;
        bool s = (v >= 1.0f);
        xs[t * BCN_ + i] = (unsigned char)s;
        if (s) v = 0.f;
    }
}

// ---------------- K2: fused Q/K/V GEMM + BN ----------------
struct QKVParams {
    const float* W[3];
    const float* g[3];
    const float* bb[3];
    const float* m[3];
    const float* vv[3];
    float* out[3];
};

#define BM 64
#define BJ 64
#define BK 32

__global__ __launch_bounds__(256) void gemm_qkv_kernel(const unsigned char* __restrict__ xs,
                                                       QKVParams p) {
    int z = blockIdx.z;
    const float* __restrict__ W = p.W[z];
    __shared__ float Ws[BK][BM + 4];
    __shared__ float Xs[BK][BJ + 4];

    int d0 = blockIdx.y * BM;
    int j0 = blockIdx.x * BJ;
    int tid = threadIdx.x;
    int tx = tid & 15, ty = tid >> 4;

    float acc[4][4];
#pragma unroll
    for (int a = 0; a < 4; a++)
#pragma unroll
        for (int b = 0; b < 4; b++) acc[a][b] = 0.f;

    for (int c0 = 0; c0 < C_; c0 += BK) {
#pragma unroll
        for (int i = 0; i < 8; i++) {
            int e = tid + i * 256;
            int r = e >> 5, cc = e & 31;
            Ws[cc][r] = W[(d0 + r) * C_ + c0 + cc];
        }
#pragma unroll
        for (int i = 0; i < 8; i++) {
            int e = tid + i * 256;
            int cc = e >> 6, jj = e & 63;
            int j = j0 + jj;
            int tb = j / N_;
            int n = j - tb * N_;
            Xs[cc][jj] = (float)xs[(tb * C_ + c0 + cc) * N_ + n];
        }
        __syncthreads();
#pragma unroll
        for (int k = 0; k < BK; k++) {
            float a[4], b[4];
            *(float4*)a = *(const float4*)&Ws[k][ty * 4];
            *(float4*)b = *(const float4*)&Xs[k][tx * 4];
#pragma unroll
            for (int di = 0; di < 4; di++)
#pragma unroll
                for (int ji = 0; ji < 4; ji++) acc[di][ji] += a[di] * b[ji];
        }
        __syncthreads();
    }

    const float* gg = p.g[z];
    const float* gb = p.bb[z];
    const float* gm = p.m[z];
    const float* gv = p.vv[z];
    float* O = p.out[z];
#pragma unroll
    for (int di = 0; di < 4; di++) {
        int d = d0 + ty * 4 + di;
        float sc = gg[d] / sqrtf(gv[d] + 1e-5f);
        float sh = gb[d] - gm[d] * sc;
#pragma unroll
        for (int ji = 0; ji < 4; ji++) {
            int j = j0 + tx * 4 + ji;
            O[d * J_ + j] = acc[di][ji] * sc + sh;
        }
    }
}

// ---------------- K3: LIF on q/k/v pre-activations ----------------
// pre layout [c, j]; spikes layout [tb, c, n]; optionally write vh (head layout) to d_out.
__global__ void lif_qkv_kernel(const float* __restrict__ pre, unsigned char* __restrict__ sp,
                               float* __restrict__ vh /* may be null */) {
    int i = blockIdx.x * blockDim.x + threadIdx.x;
    if (i >= BCN_) return;
    int c = i / (B_ * N_);
    int r = i - c * (B_ * N_);
    int b = r / N_;
    int n = r - b * N_;
    float v = 0.f;
#pragma unroll
    for (int t = 0; t < T_; t++) {
        int tb = t * B_ + b;
        float pv = pre[c * J_ + tb * N_ + n];
        v = v + (pv - v) * 0.5f;
        bool s = (v >= 1.0f);
        sp[(tb * C_ + c) * N_ + n] = (unsigned char)s;
        if (vh) {
            int h = c >> 6, dd = c & 63;
            vh[(((tb * 8) + h) * N_ + n) * 64 + dd] = s ? 1.0f : 0.0f;
        }
        if (s) v = 0.f;
    }
}

// ---------------- K4: kv = sum_n(k*v), then LIF over t ----------------
__global__ void kv_lif_kernel(const unsigned char* __restrict__ ks,
                              const unsigned char* __restrict__ vs,
                              unsigned char* __restrict__ kvs) {
    __shared__ unsigned int sk[6272];  // 128 rows * 196 bytes / 4
    __shared__ unsigned int sv[6272];
    int b = blockIdx.x >> 2;
    int c0 = (blockIdx.x & 3) * 128;
    int tid = threadIdx.x;  // 128 threads, one per channel in tile
    float vst = 0.f;
    for (int t = 0; t < T_; t++) {
        int base = ((t * B_ + b) * C_ + c0) * N_;  // byte offset, 4-aligned (196%4==0)
        const unsigned int* gk = (const unsigned int*)(ks + base);
        const unsigned int* gv = (const unsigned int*)(vs + base);
        for (int i = tid; i < 6272; i += 128) { sk[i] = gk[i]; sv[i] = gv[i]; }
        __syncthreads();
        const unsigned char* rk = ((const unsigned char*)sk) + tid * N_;
        const unsigned char* rv = ((const unsigned char*)sv) + tid * N_;
        int cnt = 0;
#pragma unroll 4
        for (int n = 0; n < N_; n++) cnt += (int)(rk[n] & rv[n]);
        float pre = (float)cnt;           // exact integer
        vst = vst + (pre - vst) * 0.5f;   // exact dyadic arithmetic
        bool s = (vst >= 1.0f);
        kvs[(t * B_ + b) * C_ + c0 + tid] = (unsigned char)s;
        if (s) vst = 0.f;
        __syncthreads();
    }
}

// ---------------- K5: out GEMM (y = q_s & kv_s) + bias + BN + residual ----------------
__global__ __launch_bounds__(256) void gemm_out_kernel(const unsigned char* __restrict__ qs,
                                                       const unsigned char* __restrict__ kvs,
                                                       const float* __restrict__ W,
                                                       const float* __restrict__ bias,
                                                       const float* __restrict__ gg,
                                                       const float* __restrict__ gb,
                                                       const float* __restrict__ gm,
                                                       const float* __restrict__ gv,
                                                       const float* __restrict__ xid,
                                                       float* __restrict__ out) {
    __shared__ float Ws[BK][BM + 4];
    __shared__ float Xs[BK][BJ + 4];

    int d0 = blockIdx.y * BM;
    int j0 = blockIdx.x * BJ;
    int tid = threadIdx.x;
    int tx = tid & 15, ty = tid >> 4;

    float acc[4][4];
#pragma unroll
    for (int a = 0; a < 4; a++)
#pragma unroll
        for (int b = 0; b < 4; b++) acc[a][b] = 0.f;

    for (int c0 = 0; c0 < C_; c0 += BK) {
#pragma unroll
        for (int i = 0; i < 8; i++) {
            int e = tid + i * 256;
            int r = e >> 5, cc = e & 31;
            Ws[cc][r] = W[(d0 + r) * C_ + c0 + cc];
        }
#pragma unroll
        for (int i = 0; i < 8; i++) {
            int e = tid + i * 256;
            int cc = e >> 6, jj = e & 63;
            int j = j0 + jj;
            int tb = j / N_;
            int n = j - tb * N_;
            int c = c0 + cc;
            unsigned char y = qs[(tb * C_ + c) * N_ + n] & kvs[tb * C_ + c];
            Xs[cc][jj] = (float)y;
        }
        __syncthreads();
#pragma unroll
        for (int k = 0; k < BK; k++) {
            float a[4], b[4];
            *(float4*)a = *(const float4*)&Ws[k][ty * 4];
            *(float4*)b = *(const float4*)&Xs[k][tx * 4];
#pragma unroll
            for (int di = 0; di < 4; di++)
#pragma unroll
                for (int ji = 0; ji < 4; ji++) acc[di][ji] += a[di] * b[ji];
        }
        __syncthreads();
    }

#pragma unroll
    for (int di = 0; di < 4; di++) {
        int d = d0 + ty * 4 + di;
        float sc = gg[d] / sqrtf(gv[d] + 1e-5f);
        float sh = gb[d] - gm[d] * sc;
        float bs = bias[d];
#pragma unroll
        for (int ji = 0; ji < 4; ji++) {
            int j = j0 + tx * 4 + ji;
            int tb = j / N_;
            int n = j - tb * N_;
            int gi = (tb * C_ + d) * N_ + n;
            float val = (acc[di][ji] + bs) * sc + sh + xid[gi];
            out[gi] = val;
        }
    }
}

// ---------------- host launch ----------------
extern "C" void kernel_launch(void* const* d_in, const int* in_sizes, int n_in,
                              void* d_out, int out_size) {
    // Detect input ordering: weights are 262144 elements.
    const float *x, *qw, *kw, *vw, *ow, *ob;
    const float *qg, *qb, *qm, *qv, *kg, *kb, *km, *kvv, *vg, *vb, *vm, *vvv, *og, *obb, *om, *ov;
    if (n_in >= 5 && in_sizes[2] == 262144) {
        // dict order: x, q_w, k_w, v_w, out_w, out_b, then q/k/v/out bn (g,b,m,v)
        x = (const float*)d_in[0];
        qw = (const float*)d_in[1];
        kw = (const float*)d_in[2];
        vw = (const float*)d_in[3];
        ow = (const float*)d_in[4];
        ob = (const float*)d_in[5];
        qg = (const float*)d_in[6];  qb = (const float*)d_in[7];  qm = (const float*)d_in[8];  qv = (const float*)d_in[9];
        kg = (const float*)d_in[10]; kb = (const float*)d_in[11]; km = (const float*)d_in[12]; kvv = (const float*)d_in[13];
        vg = (const float*)d_in[14]; vb = (const float*)d_in[15]; vm = (const float*)d_in[16]; vvv = (const float*)d_in[17];
        og = (const float*)d_in[18]; obb = (const float*)d_in[19]; om = (const float*)d_in[20]; ov = (const float*)d_in[21];
    } else {
        // signature order
        x = (const float*)d_in[0];
        qw = (const float*)d_in[1];
        qg = (const float*)d_in[2];  qb = (const float*)d_in[3];  qm = (const float*)d_in[4];  qv = (const float*)d_in[5];
        kw = (const float*)d_in[6];
        kg = (const float*)d_in[7];  kb = (const float*)d_in[8];  km = (const float*)d_in[9];  kvv = (const float*)d_in[10];
        vw = (const float*)d_in[11];
        vg = (const float*)d_in[12]; vb = (const float*)d_in[13]; vm = (const float*)d_in[14]; vvv = (const float*)d_in[15];
        ow = (const float*)d_in[16];
        ob = (const float*)d_in[17];
        og = (const float*)d_in[18]; obb = (const float*)d_in[19]; om = (const float*)d_in[20]; ov = (const float*)d_in[21];
    }

    float* out1 = (float*)d_out;                 // y + identity, [T,B,C,H,W]
    float* out2 = (float*)d_out + TBCN_;         // vh, [T,B,heads,N,hd]

    unsigned char *xs, *qs, *ks, *vs, *kvs;
    float *qp, *kp, *vp;
    cudaGetSymbolAddress((void**)&xs, g_xs);
    cudaGetSymbolAddress((void**)&qs, g_qs);
    cudaGetSymbolAddress((void**)&ks, g_ks);
    cudaGetSymbolAddress((void**)&vs, g_vs);
    cudaGetSymbolAddress((void**)&kvs, g_kvs);
    cudaGetSymbolAddress((void**)&qp, g_qp);
    cudaGetSymbolAddress((void**)&kp, g_kp);
    cudaGetSymbolAddress((void**)&vp, g_vp);

    // K1: shortcut LIF
    lif_x_kernel<<<(BCN_ + 255) / 256, 256>>>(x, xs);

    // K2: fused q/k/v GEMM + BN
    QKVParams p;
    p.W[0] = qw; p.W[1] = kw; p.W[2] = vw;
    p.g[0] = qg; p.g[1] = kg; p.g[2] = vg;
    p.bb[0] = qb; p.bb[1] = kb; p.bb[2] = vb;
    p.m[0] = qm; p.m[1] = km; p.m[2] = vm;
    p.vv[0] = qv; p.vv[1] = kvv; p.vv[2] = vvv;
    p.out[0] = qp; p.out[1] = kp; p.out[2] = vp;
    dim3 g2(J_ / BJ, C_ / BM, 3);
    gemm_qkv_kernel<<<g2, 256>>>(xs, p);

    // K3: LIF on q, k, v (v also emits vh output)
    lif_qkv_kernel<<<(BCN_ + 255) / 256, 256>>>(qp, qs, nullptr);
    lif_qkv_kernel<<<(BCN_ + 255) / 256, 256>>>(kp, ks, nullptr);
    lif_qkv_kernel<<<(BCN_ + 255) / 256, 256>>>(vp, vs, out2);

    // K4: kv reduction + LIF
    kv_lif_kernel<<<B_ * 4, 128>>>(ks, vs, kvs);

    // K5: out GEMM + bias + BN + residual
    dim3 g5(J_ / BJ, C_ / BM, 1);
    gemm_out_kernel<<<g5, 256>>>(qs, kvs, ow, ob, og, obb, om, ov, x, out1);
}

// round 8
// speedup vs baseline: 2.1647x; 2.1563x over previous
#include <cuda_runtime.h>
#include <cuda_bf16.h>
#include <stdint.h>

// Problem dims
#define T_ 4
#define B_ 32
#define C_ 512
#define N_ 196            // H*W
#define TB_ 128           // T*B
#define TBCN_ 12845056    // T*B*C*N
#define J_ 25088          // TB*N (GEMM columns)

// ---------------- static scratch (allocation-free) ----------------
__device__ __nv_bfloat16 g_ax[TBCN_];    // x spikes  [j][c]
__device__ __nv_bfloat16 g_aq[TBCN_];    // q spikes  [j][c]
__device__ __nv_bfloat16 g_ak[TBCN_];    // k spikes  [j][c]
__device__ __nv_bfloat16 g_av[TBCN_];    // v spikes  [j][c]
__device__ __nv_bfloat16 g_y[TBCN_];     // y = qs & kvs  [j][c]
__device__ float g_qp[TBCN_];            // q pre-act (post-BN) [d][j]
__device__ float g_kp[TBCN_];
__device__ float g_vp[TBCN_];
__device__ __nv_bfloat16 g_wsp[4 * 3 * 262144];  // weight bf16 splits [mat][s][d*512+c]
__device__ unsigned char g_kvs[TB_ * C_];

// ================= helpers =================
__device__ __forceinline__ uint32_t smem_u32(const void* p) {
    uint32_t a;
    asm("{ .reg .u64 t; cvta.to.shared.u64 t, %1; cvt.u32.u64 %0, t; }" : "=r"(a) : "l"(p));
    return a;
}
__device__ __forceinline__ void cp16(uint32_t dst, const void* src) {
    asm volatile("cp.async.cg.shared.global [%0], [%1], 16;" :: "r"(dst), "l"(src));
}
#define CP_COMMIT() asm volatile("cp.async.commit_group;" ::: "memory")
#define CP_WAIT1()  asm volatile("cp.async.wait_group 1;" ::: "memory")
#define CP_WAIT0()  asm volatile("cp.async.wait_group 0;" ::: "memory")

__device__ __forceinline__ void ldm_x4(uint32_t addr, uint32_t& r0, uint32_t& r1,
                                       uint32_t& r2, uint32_t& r3) {
    asm volatile("ldmatrix.sync.aligned.m8n8.x4.shared.b16 {%0,%1,%2,%3}, [%4];"
                 : "=r"(r0), "=r"(r1), "=r"(r2), "=r"(r3) : "r"(addr));
}
__device__ __forceinline__ void mma16816(float* c, const uint32_t* a, const uint32_t* b) {
    asm volatile("mma.sync.aligned.m16n8k16.row.col.f32.bf16.bf16.f32 "
                 "{%0,%1,%2,%3}, {%4,%5,%6,%7}, {%8,%9}, {%0,%1,%2,%3};"
                 : "+f"(c[0]), "+f"(c[1]), "+f"(c[2]), "+f"(c[3])
                 : "r"(a[0]), "r"(a[1]), "r"(a[2]), "r"(a[3]), "r"(b[0]), "r"(b[1]));
}

// smem tile geometry: row stride 40 bf16 (80B) -> ldmatrix conflict-free
#define RS 40
#define B_TILE_B (128 * RS * 2)          // 10240 bytes
#define A_TILE_B (128 * RS * 2)          // per split
#define BUF_B (B_TILE_B + 3 * A_TILE_B)  // 40960
#define SMEM_DYN (2 * BUF_B)             // 81920

// ---------------- K0: weight bf16 3-split ----------------
__global__ void split_w_kernel(const float* __restrict__ w0, const float* __restrict__ w1,
                               const float* __restrict__ w2, const float* __restrict__ w3,
                               __nv_bfloat16* __restrict__ out) {
    int i = blockIdx.x * 256 + threadIdx.x;  // over 4*262144
    int mat = i >> 18;
    int k = i & 262143;
    const float* W = (mat == 0) ? w0 : (mat == 1) ? w1 : (mat == 2) ? w2 : w3;
    float w = W[k];
    __nv_bfloat16 h0 = __float2bfloat16_rn(w);
    float r = w - __bfloat162float(h0);
    __nv_bfloat16 h1 = __float2bfloat16_rn(r);
    float r2 = r - __bfloat162float(h1);
    __nv_bfloat16 h2 = __float2bfloat16_rn(r2);
    __nv_bfloat16* o = out + (size_t)mat * 3 * 262144;
    o[k] = h0;
    o[262144 + k] = h1;
    o[2 * 262144 + k] = h2;
}

// ---------------- K1: shortcut LIF: x -> Ax bf16 [j][c] ----------------
__global__ __launch_bounds__(256) void lif_x_kernel(const float* __restrict__ x,
                                                    __nv_bfloat16* __restrict__ Ax) {
    __shared__ float xt[16][197];
    __shared__ float vv[16][197];
    int b = blockIdx.x, c0 = blockIdx.y * 16, tid = threadIdx.x;
    for (int i = tid; i < 16 * 197; i += 256) ((float*)vv)[i] = 0.f;
    __syncthreads();
    const __nv_bfloat16 one = __float2bfloat16_rn(1.0f);
    const __nv_bfloat16 zero = __float2bfloat16_rn(0.0f);
    for (int t = 0; t < T_; t++) {
        for (int i = tid; i < 16 * 196; i += 256) {
            int cc = i / 196, n = i - cc * 196;
            xt[cc][n] = x[(size_t)(((t * B_ + b) * C_) + c0 + cc) * N_ + n];
        }
        __syncthreads();
        int jb = (t * B_ + b) * N_;
        for (int i = tid; i < 16 * 196; i += 256) {
            int n = i >> 4, cc = i & 15;
            float v = vv[cc][n];
            v += (xt[cc][n] - v) * 0.5f;
            bool s = (v >= 1.0f);
            Ax[(size_t)(jb + n) * C_ + c0 + cc] = s ? one : zero;
            vv[cc][n] = s ? 0.f : v;
        }
        __syncthreads();
    }
}

// ---------------- K3: LIF on q/k/v pre-acts: P[d][j] -> A bf16 [j][d] (+vh) ----------------
__global__ __launch_bounds__(256) void lif_qkv_kernel(const float* __restrict__ qp,
                                                      const float* __restrict__ kp,
                                                      const float* __restrict__ vp,
                                                      __nv_bfloat16* __restrict__ Aq,
                                                      __nv_bfloat16* __restrict__ Ak,
                                                      __nv_bfloat16* __restrict__ Av,
                                                      float* __restrict__ vh) {
    __shared__ float pt[16][197];
    __shared__ float vv[16][197];
    int z = blockIdx.z;
    const float* __restrict__ P = (z == 0) ? qp : (z == 1) ? kp : vp;
    __nv_bfloat16* __restrict__ A = (z == 0) ? Aq : (z == 1) ? Ak : Av;
    int b = blockIdx.x, d0 = blockIdx.y * 16, tid = threadIdx.x;
    for (int i = tid; i < 16 * 197; i += 256) ((float*)vv)[i] = 0.f;
    __syncthreads();
    const __nv_bfloat16 one = __float2bfloat16_rn(1.0f);
    const __nv_bfloat16 zero = __float2bfloat16_rn(0.0f);
    for (int t = 0; t < T_; t++) {
        int jb = (t * B_ + b) * N_;
        for (int i = tid; i < 16 * 196; i += 256) {
            int dd = i / 196, n = i - dd * 196;
            pt[dd][n] = P[(size_t)(d0 + dd) * J_ + jb + n];
        }
        __syncthreads();
        for (int i = tid; i < 16 * 196; i += 256) {
            int n = i >> 4, dd = i & 15;
            float v = vv[dd][n];
            v += (pt[dd][n] - v) * 0.5f;
            bool s = (v >= 1.0f);
            A[(size_t)(jb + n) * C_ + d0 + dd] = s ? one : zero;
            if (z == 2) {
                int c = d0 + dd;
                vh[(size_t)(t * B_ + b) * 100352 + (c >> 6) * 12544 + n * 64 + (c & 63)] = s ? 1.0f : 0.0f;
            }
            vv[dd][n] = s ? 0.f : v;
        }
        __syncthreads();
    }
}

// ---------------- K4: kv = sum_n(k&v), LIF over t ----------------
__global__ __launch_bounds__(512) void kv_lif_kernel(const __nv_bfloat16* __restrict__ Ak,
                                                     const __nv_bfloat16* __restrict__ Av,
                                                     unsigned char* __restrict__ kvs) {
    int b = blockIdx.x;
    int c = threadIdx.x;
    const unsigned short* ak = (const unsigned short*)Ak;
    const unsigned short* av = (const unsigned short*)Av;
    float vst = 0.f;
    for (int t = 0; t < T_; t++) {
        int jb = (t * B_ + b) * N_;
        int cnt = 0;
#pragma unroll 4
        for (int n = 0; n < N_; n++) {
            size_t o = (size_t)(jb + n) * C_ + c;
            cnt += ((ak[o] & av[o]) != 0);
        }
        vst += ((float)cnt - vst) * 0.5f;
        bool s = (vst >= 1.0f);
        kvs[(t * B_ + b) * C_ + c] = (unsigned char)s;
        if (s) vst = 0.f;
    }
}

// ---------------- K4b: Y[j][c] = Aq[j][c] masked by kvs[tb][c] ----------------
__global__ __launch_bounds__(256) void ymask_kernel(const __nv_bfloat16* __restrict__ Aq,
                                                    const unsigned char* __restrict__ kvs,
                                                    __nv_bfloat16* __restrict__ Y) {
    int idx = blockIdx.x * 256 + threadIdx.x;  // 4 bf16 per thread
    int e = idx * 4;
    int j = e >> 9;
    int c = e & 511;
    int tb = j / N_;
    uint2 a = ((const uint2*)Aq)[idx];
    uchar4 kb = *(const uchar4*)(kvs + tb * C_ + c);
    uint32_t mx = (kb.x ? 0xFFFFu : 0u) | (kb.y ? 0xFFFF0000u : 0u);
    uint32_t my = (kb.z ? 0xFFFFu : 0u) | (kb.w ? 0xFFFF0000u : 0u);
    uint2 o;
    o.x = a.x & mx;
    o.y = a.y & my;
    ((uint2*)Y)[idx] = o;
}

// ---------------- HMMA GEMM: P[d][j] = sum_s Wsplit_s[d][c] * Act[j][c] ----------------
struct GemmArgs {
    const __nv_bfloat16* Bact;
    const __nv_bfloat16* W[3];   // per-z: base of 3 contiguous bf16 splits
    const float* g[3];
    const float* bb[3];
    const float* m[3];
    const float* vv[3];
    float* out[3];
    const float* bias;  // OUT only
    const float* xid;   // OUT only
};

template <bool OUT>
__global__ __launch_bounds__(256) void gemm_mma(GemmArgs ga) {
    extern __shared__ char sm[];
    __shared__ float scs[128];
    __shared__ float shs[128];
    uint32_t sb = smem_u32(sm);
    int tid = threadIdx.x, lane = tid & 31, wid = tid >> 5;
    int wd = wid >> 2, wj = wid & 3;            // warps: 2 (d) x 4 (j)
    int j0 = blockIdx.x * 128, d0 = blockIdx.y * 128, z = blockIdx.z;
    const __nv_bfloat16* __restrict__ Wz = ga.W[z];
    const __nv_bfloat16* __restrict__ Ba = ga.Bact;

    // BN scale/shift
    if (tid < 128) {
        int d = d0 + tid;
        float sc = ga.g[z][d] / sqrtf(ga.vv[z][d] + 1e-5f);
        float sh = ga.bb[z][d] - ga.m[z][d] * sc;
        if (OUT) sh += ga.bias[d] * sc;
        scs[tid] = sc;
        shs[tid] = sh;
    }

    float acc[4][4][4];
#pragma unroll
    for (int a = 0; a < 4; a++)
#pragma unroll
        for (int b = 0; b < 4; b++)
#pragma unroll
            for (int c = 0; c < 4; c++) acc[a][b][c] = 0.f;

    // thread's load slots
    int brow = tid >> 2, bseg = tid & 3;  // B: 2 iters (rows 0-63, 64-127)

    auto load_chunk = [&](int buf, int it) {
        int c0 = it * 32;
        uint32_t base = sb + buf * BUF_B;
#pragma unroll
        for (int i = 0; i < 2; i++) {
            int row = brow + i * 64;
            cp16(base + row * (RS * 2) + bseg * 16,
                 Ba + (size_t)(j0 + row) * C_ + c0 + bseg * 8);
        }
#pragma unroll
        for (int i = 0; i < 6; i++) {
            int e = tid + i * 256;
            int s = e >> 9;
            int row = (e >> 2) & 127;
            int seg = e & 3;
            cp16(base + B_TILE_B + s * A_TILE_B + row * (RS * 2) + seg * 16,
                 Wz + (size_t)s * 262144 + (size_t)(d0 + row) * C_ + c0 + seg * 8);
        }
    };

    // ldmatrix address offsets
    int sub = lane >> 3, l7 = lane & 7;
    int a_r = (sub & 1) * 8 + l7, a_c2 = (sub >> 1) * 8;   // A pattern
    int b_r = (sub >> 1) * 8 + l7, b_c2 = (sub & 1) * 8;   // B pattern

    load_chunk(0, 0);
    CP_COMMIT();

    for (int it = 0; it < 16; it++) {
        if (it < 15) {
            load_chunk((it + 1) & 1, it + 1);
            CP_COMMIT();
            CP_WAIT1();
        } else {
            CP_WAIT0();
        }
        __syncthreads();

        uint32_t base = sb + (it & 1) * BUF_B;
        uint32_t bB = base;
        uint32_t bA = base + B_TILE_B;

        // B fragments: [k16][ntile][2]
        uint32_t bf[2][4][2];
#pragma unroll
        for (int k16 = 0; k16 < 2; k16++)
#pragma unroll
            for (int np = 0; np < 2; np++) {
                int row = wj * 32 + np * 16 + b_r;
                int col = k16 * 16 + b_c2;
                uint32_t addr = bB + row * (RS * 2) + col * 2;
                ldm_x4(addr, bf[k16][np * 2][0], bf[k16][np * 2][1],
                       bf[k16][np * 2 + 1][0], bf[k16][np * 2 + 1][1]);
            }

#pragma unroll
        for (int s = 0; s < 3; s++) {
#pragma unroll
            for (int k16 = 0; k16 < 2; k16++) {
#pragma unroll
                for (int mi = 0; mi < 4; mi++) {
                    uint32_t af[4];
                    int row = wd * 64 + mi * 16 + a_r;
                    int col = k16 * 16 + a_c2;
                    uint32_t addr = bA + s * A_TILE_B + row * (RS * 2) + col * 2;
                    ldm_x4(addr, af[0], af[1], af[2], af[3]);
#pragma unroll
                    for (int ni = 0; ni < 4; ni++)
                        mma16816(acc[mi][ni], af, bf[k16][ni]);
                }
            }
        }
        __syncthreads();
    }

    // epilogue
    int r = lane >> 2, cq = (lane & 3) * 2;
#pragma unroll
    for (int mi = 0; mi < 4; mi++) {
        int dl0 = wd * 64 + mi * 16 + r;      // local d rows dl0, dl0+8
#pragma unroll
        for (int ni = 0; ni < 4; ni++) {
            int jj = j0 + wj * 32 + ni * 8 + cq;
            float v00 = acc[mi][ni][0] * scs[dl0] + shs[dl0];
            float v01 = acc[mi][ni][1] * scs[dl0] + shs[dl0];
            float v10 = acc[mi][ni][2] * scs[dl0 + 8] + shs[dl0 + 8];
            float v11 = acc[mi][ni][3] * scs[dl0 + 8] + shs[dl0 + 8];
            if (OUT) {
                const float* xid = ga.xid;
                float* o = ga.out[0];
#pragma unroll
                for (int e = 0; e < 4; e++) {
                    int dd = d0 + dl0 + (e >> 1) * 8;
                    int j = jj + (e & 1);
                    int tb = j / N_;
                    int n = j - tb * N_;
                    size_t gi = (size_t)(tb * C_ + dd) * N_ + n;
                    float val = (e == 0) ? v00 : (e == 1) ? v01 : (e == 2) ? v10 : v11;
                    o[gi] = val + xid[gi];
                }
            } else {
                float* P = ga.out[z];
                *(float2*)(P + (size_t)(d0 + dl0) * J_ + jj) = make_float2(v00, v01);
                *(float2*)(P + (size_t)(d0 + dl0 + 8) * J_ + jj) = make_float2(v10, v11);
            }
        }
    }
}

// ---------------- host launch ----------------
extern "C" void kernel_launch(void* const* d_in, const int* in_sizes, int n_in,
                              void* d_out, int out_size) {
    const float *x, *qw, *kw, *vw, *ow, *ob;
    const float *qg, *qb, *qm, *qv, *kg, *kb, *km, *kvv, *vg, *vb, *vm, *vvv, *og, *obb, *om, *ov;
    if (n_in >= 5 && in_sizes[2] == 262144) {
        x = (const float*)d_in[0];
        qw = (const float*)d_in[1]; kw = (const float*)d_in[2];
        vw = (const float*)d_in[3]; ow = (const float*)d_in[4];
        ob = (const float*)d_in[5];
        qg = (const float*)d_in[6];  qb = (const float*)d_in[7];  qm = (const float*)d_in[8];  qv = (const float*)d_in[9];
        kg = (const float*)d_in[10]; kb = (const float*)d_in[11]; km = (const float*)d_in[12]; kvv = (const float*)d_in[13];
        vg = (const float*)d_in[14]; vb = (const float*)d_in[15]; vm = (const float*)d_in[16]; vvv = (const float*)d_in[17];
        og = (const float*)d_in[18]; obb = (const float*)d_in[19]; om = (const float*)d_in[20]; ov = (const float*)d_in[21];
    } else {
        x = (const float*)d_in[0];
        qw = (const float*)d_in[1];
        qg = (const float*)d_in[2];  qb = (const float*)d_in[3];  qm = (const float*)d_in[4];  qv = (const float*)d_in[5];
        kw = (const float*)d_in[6];
        kg = (const float*)d_in[7];  kb = (const float*)d_in[8];  km = (const float*)d_in[9];  kvv = (const float*)d_in[10];
        vw = (const float*)d_in[11];
        vg = (const float*)d_in[12]; vb = (const float*)d_in[13]; vm = (const float*)d_in[14]; vvv = (const float*)d_in[15];
        ow = (const float*)d_in[16]; ob = (const float*)d_in[17];
        og = (const float*)d_in[18]; obb = (const float*)d_in[19]; om = (const float*)d_in[20]; ov = (const float*)d_in[21];
    }

    float* out1 = (float*)d_out;
    float* out2 = (float*)d_out + TBCN_;

    __nv_bfloat16 *ax, *aq, *ak, *av, *yy, *wsp;
    float *qp, *kp, *vp;
    unsigned char* kvs;
    cudaGetSymbolAddress((void**)&ax, g_ax);
    cudaGetSymbolAddress((void**)&aq, g_aq);
    cudaGetSymbolAddress((void**)&ak, g_ak);
    cudaGetSymbolAddress((void**)&av, g_av);
    cudaGetSymbolAddress((void**)&yy, g_y);
    cudaGetSymbolAddress((void**)&wsp, g_wsp);
    cudaGetSymbolAddress((void**)&qp, g_qp);
    cudaGetSymbolAddress((void**)&kp, g_kp);
    cudaGetSymbolAddress((void**)&vp, g_vp);
    cudaGetSymbolAddress((void**)&kvs, g_kvs);

    cudaFuncSetAttribute(gemm_mma<false>, cudaFuncAttributeMaxDynamicSharedMemorySize, SMEM_DYN);
    cudaFuncSetAttribute(gemm_mma<true>, cudaFuncAttributeMaxDynamicSharedMemorySize, SMEM_DYN);

    // K0: weight splits
    split_w_kernel<<<4096, 256>>>(qw, kw, vw, ow, wsp);

    // K1: shortcut LIF -> Ax
    dim3 g1(B_, 32);
    lif_x_kernel<<<g1, 256>>>(x, ax);

    // G1: q/k/v GEMMs (bf16 3-split HMMA) -> qp/kp/vp (post-BN)
    GemmArgs a1;
    a1.Bact = ax;
    a1.W[0] = wsp; a1.W[1] = wsp + 3 * 262144; a1.W[2] = wsp + 6 * 262144;
    a1.g[0] = qg; a1.g[1] = kg; a1.g[2] = vg;
    a1.bb[0] = qb; a1.bb[1] = kb; a1.bb[2] = vb;
    a1.m[0] = qm; a1.m[1] = km; a1.m[2] = vm;
    a1.vv[0] = qv; a1.vv[1] = kvv; a1.vv[2] = vvv;
    a1.out[0] = qp; a1.out[1] = kp; a1.out[2] = vp;
    a1.bias = nullptr; a1.xid = nullptr;
    dim3 gg1(J_ / 128, C_ / 128, 3);
    gemm_mma<false><<<gg1, 256, SMEM_DYN>>>(a1);

    // K3: LIF on q/k/v -> Aq/Ak/Av (+ vh)
    dim3 g3(B_, 32, 3);
    lif_qkv_kernel<<<g3, 256>>>(qp, kp, vp, aq, ak, av, out2);

    // K4: kv reduction + LIF
    kv_lif_kernel<<<B_, 512>>>(ak, av, kvs);

    // K4b: Y = Aq masked by kvs
    ymask_kernel<<<TBCN_ / 4 / 256, 256>>>(aq, kvs, yy);

    // G2: out GEMM + bias + BN + residual
    GemmArgs a2;
    a2.Bact = yy;
    a2.W[0] = wsp + 9 * 262144; a2.W[1] = nullptr; a2.W[2] = nullptr;
    a2.g[0] = og; a2.bb[0] = obb; a2.m[0] = om; a2.vv[0] = ov;
    a2.g[1] = a2.g[2] = og; a2.bb[1] = a2.bb[2] = obb; a2.m[1] = a2.m[2] = om; a2.vv[1] = a2.vv[2] = ov;
    a2.out[0] = out1; a2.out[1] = a2.out[2] = out1;
    a2.bias = ob; a2.xid = x;
    dim3 gg2(J_ / 128, C_ / 128, 1);
    gemm_mma<true><<<gg2, 256, SMEM_DYN>>>(a2);
}

// round 14
// speedup vs baseline: 2.6153x; 1.2082x over previous
#include <cuda_runtime.h>
#include <cuda_bf16.h>
#include <stdint.h>

// Problem dims
#define T_ 4
#define B_ 32
#define C_ 512
#define N_ 196            // H*W
#define TB_ 128           // T*B
#define TBCN_ 12845056    // T*B*C*N
#define J_ 25088          // TB*N (GEMM columns), ordered j = (b*196+n)*4 + t

// ---------------- static scratch (allocation-free) ----------------
__device__ __nv_bfloat16 g_ax[TBCN_];    // x spikes  [j][c]
__device__ __nv_bfloat16 g_aq[TBCN_];    // q spikes  [j][c]
__device__ __nv_bfloat16 g_ak[TBCN_];    // k spikes  [j][c]
__device__ __nv_bfloat16 g_av[TBCN_];    // v spikes  [j][c]
__device__ __nv_bfloat16 g_wsp[4 * 3 * 262144];  // weight bf16 splits [mat][s][d*512+c]
__device__ unsigned char g_kvs[TB_ * C_];        // kv spikes [tb][c]

// ================= helpers =================
__device__ __forceinline__ uint32_t smem_u32(const void* p) {
    uint32_t a;
    asm("{ .reg .u64 t; cvta.to.shared.u64 t, %1; cvt.u32.u64 %0, t; }" : "=r"(a) : "l"(p));
    return a;
}
__device__ __forceinline__ void cp16(uint32_t dst, const void* src) {
    asm volatile("cp.async.cg.shared.global [%0], [%1], 16;" :: "r"(dst), "l"(src));
}
#define CP_COMMIT() asm volatile("cp.async.commit_group;" ::: "memory")
#define CP_WAIT1()  asm volatile("cp.async.wait_group 1;" ::: "memory")
#define CP_WAIT0()  asm volatile("cp.async.wait_group 0;" ::: "memory")

__device__ __forceinline__ void ldm_x4(uint32_t addr, uint32_t& r0, uint32_t& r1,
                                       uint32_t& r2, uint32_t& r3) {
    asm volatile("ldmatrix.sync.aligned.m8n8.x4.shared.b16 {%0,%1,%2,%3}, [%4];"
                 : "=r"(r0), "=r"(r1), "=r"(r2), "=r"(r3) : "r"(addr));
}
__device__ __forceinline__ void mma16816(float* c, const uint32_t* a, const uint32_t* b) {
    asm volatile("mma.sync.aligned.m16n8k16.row.col.f32.bf16.bf16.f32 "
                 "{%0,%1,%2,%3}, {%4,%5,%6,%7}, {%8,%9}, {%0,%1,%2,%3};"
                 : "+f"(c[0]), "+f"(c[1]), "+f"(c[2]), "+f"(c[3])
                 : "r"(a[0]), "r"(a[1]), "r"(a[2]), "r"(a[3]), "r"(b[0]), "r"(b[1]));
}

// smem tile geometry: row stride 40 bf16 (80B) -> ldmatrix conflict-free
#define RS 40
#define B_TILE_B (128 * RS * 2)          // 10240 bytes
#define A_TILE_B (128 * RS * 2)          // per split
#define BUF_B (B_TILE_B + 3 * A_TILE_B)  // 40960
#define SMEM_DYN (2 * BUF_B)             // 81920 (also >= 128*133*4 = 68096 for epilogue)

// ---------------- K0: weight bf16 3-split ----------------
__global__ void split_w_kernel(const float* __restrict__ w0, const float* __restrict__ w1,
                               const float* __restrict__ w2, const float* __restrict__ w3,
                               __nv_bfloat16* __restrict__ out) {
    int i = blockIdx.x * 256 + threadIdx.x;  // over 4*262144
    int mat = i >> 18;
    int k = i & 262143;
    const float* W = (mat == 0) ? w0 : (mat == 1) ? w1 : (mat == 2) ? w2 : w3;
    float w = W[k];
    __nv_bfloat16 h0 = __float2bfloat16_rn(w);
    float r = w - __bfloat162float(h0);
    __nv_bfloat16 h1 = __float2bfloat16_rn(r);
    float r2 = r - __bfloat162float(h1);
    __nv_bfloat16 h2 = __float2bfloat16_rn(r2);
    __nv_bfloat16* o = out + (size_t)mat * 3 * 262144;
    o[k] = h0;
    o[262144 + k] = h1;
    o[2 * 262144 + k] = h2;
}

// ---------------- K1: shortcut LIF: x[t][b][c][n] -> Ax bf16 [j][c], j=(b*196+n)*4+t ----
__global__ __launch_bounds__(256) void lif_x_kernel(const float* __restrict__ x,
                                                    __nv_bfloat16* __restrict__ Ax) {
    __shared__ float xt[16][197];
    __shared__ float vv[16][197];
    int b = blockIdx.x, c0 = blockIdx.y * 16, tid = threadIdx.x;
    for (int i = tid; i < 16 * 197; i += 256) ((float*)vv)[i] = 0.f;
    __syncthreads();
    const __nv_bfloat16 one = __float2bfloat16_rn(1.0f);
    const __nv_bfloat16 zero = __float2bfloat16_rn(0.0f);
    for (int t = 0; t < T_; t++) {
        for (int i = tid; i < 16 * 196; i += 256) {
            int cc = i / 196, n = i - cc * 196;
            xt[cc][n] = x[(size_t)(((t * B_ + b) * C_) + c0 + cc) * N_ + n];
        }
        __syncthreads();
        for (int i = tid; i < 16 * 196; i += 256) {
            int n = i >> 4, cc = i & 15;
            float v = vv[cc][n];
            v += (xt[cc][n] - v) * 0.5f;
            bool s = (v >= 1.0f);
            int j = (b * 196 + n) * 4 + t;
            Ax[(size_t)j * C_ + c0 + cc] = s ? one : zero;
            vv[cc][n] = s ? 0.f : v;
        }
        __syncthreads();
    }
}

// ---------------- K4: kv = sum_n(k&v), LIF over t -> kvs[tb][c] ----------------
__global__ __launch_bounds__(256) void kv_lif_kernel(const __nv_bfloat16* __restrict__ Ak,
                                                     const __nv_bfloat16* __restrict__ Av,
                                                     unsigned char* __restrict__ kvs) {
    __shared__ int red[4][4][64];  // [nq][t][c]
    int b = blockIdx.x, c0 = blockIdx.y * 64;
    int cc = threadIdx.x & 63, q = threadIdx.x >> 6;
    const unsigned short* ak = (const unsigned short*)Ak;
    const unsigned short* av = (const unsigned short*)Av;
    int cnt[4] = {0, 0, 0, 0};
    for (int n = q * 49; n < (q + 1) * 49; n++) {
        size_t base = (size_t)((b * 196 + n) * 4) * C_ + c0 + cc;
#pragma unroll
        for (int t = 0; t < 4; t++)
            cnt[t] += ((ak[base + t * C_] & av[base + t * C_]) != 0);
    }
#pragma unroll
    for (int t = 0; t < 4; t++) red[q][t][cc] = cnt[t];
    __syncthreads();
    if (q == 0) {
        float v = 0.f;
#pragma unroll
        for (int t = 0; t < 4; t++) {
            float pre = (float)(red[0][t][cc] + red[1][t][cc] + red[2][t][cc] + red[3][t][cc]);
            v += (pre - v) * 0.5f;
            bool s = (v >= 1.0f);
            kvs[(t * B_ + b) * C_ + c0 + cc] = (unsigned char)s;
            if (s) v = 0.f;
        }
    }
}

// ---------------- HMMA GEMM ----------------
// QKV (!OUT): P = W_z * Ax, BN, then fused 4-step LIF over adjacent t columns;
//             writes bf16 spikes to Asp[z] (+ vh for z==2).
// OUT:        B operand = Aq masked in-smem by kvs; epilogue BN+bias+residual -> out.
struct GemmArgs {
    const __nv_bfloat16* Bact;
    const __nv_bfloat16* W[3];
    const float* g[3];
    const float* bb[3];
    const float* m[3];
    const float* vv[3];
    __nv_bfloat16* Asp[3];   // QKV: spike outputs
    float* vh;               // QKV z==2
    const unsigned char* kvs;  // OUT
    float* out;              // OUT
    const float* bias;       // OUT
    const float* xid;        // OUT
};

template <bool OUT>
__global__ __launch_bounds__(256) void gemm_mma(GemmArgs ga) {
    extern __shared__ char sm[];
    __shared__ float scs[128];
    __shared__ float shs[128];
    uint32_t sb = smem_u32(sm);
    int tid = threadIdx.x, lane = tid & 31, wid = tid >> 5;
    int wd = wid >> 2, wj = wid & 3;            // warps: 2 (d) x 4 (j)
    int j0 = blockIdx.x * 128, d0 = blockIdx.y * 128, z = blockIdx.z;
    const __nv_bfloat16* __restrict__ Wz = ga.W[z];
    const __nv_bfloat16* __restrict__ Ba = ga.Bact;

    // BN scale/shift
    if (tid < 128) {
        int d = d0 + tid;
        float sc = ga.g[z][d] / sqrtf(ga.vv[z][d] + 1e-5f);
        float sh = ga.bb[z][d] - ga.m[z][d] * sc;
        if (OUT) sh += ga.bias[d] * sc;
        scs[tid] = sc;
        shs[tid] = sh;
    }

    float acc[4][4][4];
#pragma unroll
    for (int a = 0; a < 4; a++)
#pragma unroll
        for (int b = 0; b < 4; b++)
#pragma unroll
            for (int c = 0; c < 4; c++) acc[a][b][c] = 0.f;

    int brow = tid >> 2, bseg = tid & 3;  // B slots: rows brow, brow+64; 8 cols each

    // OUT: per-thread tb of its two B rows (constant across chunks)
    int tb_r[2];
    if (OUT) {
#pragma unroll
        for (int i = 0; i < 2; i++) {
            int j = j0 + brow + i * 64;
            int t = j & 3, g = j >> 2, b = g / 196;
            tb_r[i] = t * B_ + b;
        }
    }

    auto load_chunk = [&](int buf, int it) {
        int c0 = it * 32;
        uint32_t base = sb + buf * BUF_B;
#pragma unroll
        for (int i = 0; i < 2; i++) {
            int row = brow + i * 64;
            cp16(base + row * (RS * 2) + bseg * 16,
                 Ba + (size_t)(j0 + row) * C_ + c0 + bseg * 8);
        }
#pragma unroll
        for (int i = 0; i < 6; i++) {
            int e = tid + i * 256;
            int s = e >> 9;
            int row = (e >> 2) & 127;
            int seg = e & 3;
            cp16(base + B_TILE_B + s * A_TILE_B + row * (RS * 2) + seg * 16,
                 Wz + (size_t)s * 262144 + (size_t)(d0 + row) * C_ + c0 + seg * 8);
        }
    };

    // ldmatrix address patterns
    int sub = lane >> 3, l7 = lane & 7;
    int a_r = (sub & 1) * 8 + l7, a_c2 = (sub >> 1) * 8;
    int b_r = (sub >> 1) * 8 + l7, b_c2 = (sub & 1) * 8;

    load_chunk(0, 0);
    CP_COMMIT();

    for (int it = 0; it < 16; it++) {
        if (it < 15) {
            load_chunk((it + 1) & 1, it + 1);
            CP_COMMIT();
            CP_WAIT1();
        } else {
            CP_WAIT0();
        }

        // OUT: mask own B slots with kvs (this thread's own cp.async data, now complete)
        if (OUT) {
            int c0 = it * 32;
#pragma unroll
            for (int i = 0; i < 2; i++) {
                int row = brow + i * 64;
                const unsigned char* kp = ga.kvs + tb_r[i] * C_ + c0 + bseg * 8;
                uint32_t k0 = *(const uint32_t*)kp;
                uint32_t k1 = *(const uint32_t*)(kp + 4);
                uint4* sp = (uint4*)(sm + (it & 1) * BUF_B + row * (RS * 2) + bseg * 16);
                uint4 w = *sp;
                w.x &= ((k0 & 0xFFu) ? 0xFFFFu : 0u) | ((k0 & 0xFF00u) ? 0xFFFF0000u : 0u);
                w.y &= ((k0 & 0xFF0000u) ? 0xFFFFu : 0u) | ((k0 & 0xFF000000u) ? 0xFFFF0000u : 0u);
                w.z &= ((k1 & 0xFFu) ? 0xFFFFu : 0u) | ((k1 & 0xFF00u) ? 0xFFFF0000u : 0u);
                w.w &= ((k1 & 0xFF0000u) ? 0xFFFFu : 0u) | ((k1 & 0xFF000000u) ? 0xFFFF0000u : 0u);
                *sp = w;
            }
        }
        __syncthreads();

        uint32_t base = sb + (it & 1) * BUF_B;
        uint32_t bB = base;
        uint32_t bA = base + B_TILE_B;

        uint32_t bf[2][4][2];
#pragma unroll
        for (int k16 = 0; k16 < 2; k16++)
#pragma unroll
            for (int np = 0; np < 2; np++) {
                int row = wj * 32 + np * 16 + b_r;
                int col = k16 * 16 + b_c2;
                uint32_t addr = bB + row * (RS * 2) + col * 2;
                ldm_x4(addr, bf[k16][np * 2][0], bf[k16][np * 2][1],
                       bf[k16][np * 2 + 1][0], bf[k16][np * 2 + 1][1]);
            }

#pragma unroll
        for (int s = 0; s < 3; s++) {
#pragma unroll
            for (int k16 = 0; k16 < 2; k16++) {
#pragma unroll
                for (int mi = 0; mi < 4; mi++) {
                    uint32_t af[4];
                    int row = wd * 64 + mi * 16 + a_r;
                    int col = k16 * 16 + a_c2;
                    uint32_t addr = bA + s * A_TILE_B + row * (RS * 2) + col * 2;
                    ldm_x4(addr, af[0], af[1], af[2], af[3]);
#pragma unroll
                    for (int ni = 0; ni < 4; ni++)
                        mma16816(acc[mi][ni], af, bf[k16][ni]);
                }
            }
        }
        __syncthreads();
    }

    // ---------------- epilogue ----------------
    int r = lane >> 2, cq = (lane & 3) * 2;
    if (OUT) {
        const float* xid = ga.xid;
        float* o = ga.out;
#pragma unroll
        for (int mi = 0; mi < 4; mi++) {
            int dl0 = wd * 64 + mi * 16 + r;
#pragma unroll
            for (int ni = 0; ni < 4; ni++) {
                int jj = j0 + wj * 32 + ni * 8 + cq;
                float v[4];
                v[0] = acc[mi][ni][0] * scs[dl0] + shs[dl0];
                v[1] = acc[mi][ni][1] * scs[dl0] + shs[dl0];
                v[2] = acc[mi][ni][2] * scs[dl0 + 8] + shs[dl0 + 8];
                v[3] = acc[mi][ni][3] * scs[dl0 + 8] + shs[dl0 + 8];
#pragma unroll
                for (int e = 0; e < 4; e++) {
                    int dd = d0 + dl0 + (e >> 1) * 8;
                    int j = jj + (e & 1);
                    int t = j & 3, g = j >> 2;
                    int b = g / 196, n = g - b * 196;
                    size_t gi = (size_t)((t * B_ + b) * C_ + dd) * N_ + n;
                    o[gi] = v[e] + xid[gi];
                }
            }
        }
    } else {
        // stage BN'd pre-acts to smem [d][j_local], stride 133 (odd -> LIF reads
        // conflict-free). NOTE: scalar stores only — index parity alternates with
        // dl0, so float2 here would be a misaligned address.
        float* S = (float*)sm;
#pragma unroll
        for (int mi = 0; mi < 4; mi++) {
            int dl0 = wd * 64 + mi * 16 + r;
#pragma unroll
            for (int ni = 0; ni < 4; ni++) {
                int jj = wj * 32 + ni * 8 + cq;
                S[dl0 * 133 + jj] = acc[mi][ni][0] * scs[dl0] + shs[dl0];
                S[dl0 * 133 + jj + 1] = acc[mi][ni][1] * scs[dl0] + shs[dl0];
                S[(dl0 + 8) * 133 + jj] = acc[mi][ni][2] * scs[dl0 + 8] + shs[dl0 + 8];
                S[(dl0 + 8) * 133 + jj + 1] = acc[mi][ni][3] * scs[dl0 + 8] + shs[dl0 + 8];
            }
        }
        __syncthreads();
        const __nv_bfloat16 one = __float2bfloat16_rn(1.0f);
        const __nv_bfloat16 zero = __float2bfloat16_rn(0.0f);
        __nv_bfloat16* A = ga.Asp[z];
#pragma unroll 1
        for (int p = 0; p < 16; p++) {
            int sid = p * 256 + tid;
            int d = sid & 127, gl = sid >> 7;  // gl in 0..31
            int jbase = j0 + gl * 4;
            int g = jbase >> 2;
            int b = g / 196, n = g - b * 196;
            int c = d0 + d;
            float v = 0.f;
#pragma unroll
            for (int t = 0; t < 4; t++) {
                float pre = S[d * 133 + gl * 4 + t];
                v += (pre - v) * 0.5f;
                bool s = (v >= 1.0f);
                A[(size_t)(jbase + t) * C_ + c] = s ? one : zero;
                if (z == 2) {
                    ga.vh[(size_t)(t * B_ + b) * 100352 + (c >> 6) * 12544 + n * 64 + (c & 63)] =
                        s ? 1.0f : 0.0f;
                }
                if (s) v = 0.f;
            }
        }
    }
}

// ---------------- host launch ----------------
extern "C" void kernel_launch(void* const* d_in, const int* in_sizes, int n_in,
                              void* d_out, int out_size) {
    const float *x, *qw, *kw, *vw, *ow, *ob;
    const float *qg, *qb, *qm, *qv, *kg, *kb, *km, *kvv, *vg, *vb, *vm, *vvv, *og, *obb, *om, *ov;
    if (n_in >= 5 && in_sizes[2] == 262144) {
        x = (const float*)d_in[0];
        qw = (const float*)d_in[1]; kw = (const float*)d_in[2];
        vw = (const float*)d_in[3]; ow = (const float*)d_in[4];
        ob = (const float*)d_in[5];
        qg = (const float*)d_in[6];  qb = (const float*)d_in[7];  qm = (const float*)d_in[8];  qv = (const float*)d_in[9];
        kg = (const float*)d_in[10]; kb = (const float*)d_in[11]; km = (const float*)d_in[12]; kvv = (const float*)d_in[13];
        vg = (const float*)d_in[14]; vb = (const float*)d_in[15]; vm = (const float*)d_in[16]; vvv = (const float*)d_in[17];
        og = (const float*)d_in[18]; obb = (const float*)d_in[19]; om = (const float*)d_in[20]; ov = (const float*)d_in[21];
    } else {
        x = (const float*)d_in[0];
        qw = (const float*)d_in[1];
        qg = (const float*)d_in[2];  qb = (const float*)d_in[3];  qm = (const float*)d_in[4];  qv = (const float*)d_in[5];
        kw = (const float*)d_in[6];
        kg = (const float*)d_in[7];  kb = (const float*)d_in[8];  km = (const float*)d_in[9];  kvv = (const float*)d_in[10];
        vw = (const float*)d_in[11];
        vg = (const float*)d_in[12]; vb = (const float*)d_in[13]; vm = (const float*)d_in[14]; vvv = (const float*)d_in[15];
        ow = (const float*)d_in[16]; ob = (const float*)d_in[17];
        og = (const float*)d_in[18]; obb = (const float*)d_in[19]; om = (const float*)d_in[20]; ov = (const float*)d_in[21];
    }

    float* out1 = (float*)d_out;
    float* out2 = (float*)d_out + TBCN_;

    __nv_bfloat16 *ax, *aq, *ak, *av, *wsp;
    unsigned char* kvs;
    cudaGetSymbolAddress((void**)&ax, g_ax);
    cudaGetSymbolAddress((void**)&aq, g_aq);
    cudaGetSymbolAddress((void**)&ak, g_ak);
    cudaGetSymbolAddress((void**)&av, g_av);
    cudaGetSymbolAddress((void**)&wsp, g_wsp);
    cudaGetSymbolAddress((void**)&kvs, g_kvs);

    cudaFuncSetAttribute(gemm_mma<false>, cudaFuncAttributeMaxDynamicSharedMemorySize, SMEM_DYN);
    cudaFuncSetAttribute(gemm_mma<true>, cudaFuncAttributeMaxDynamicSharedMemorySize, SMEM_DYN);

    // K0: weight splits
    split_w_kernel<<<4096, 256>>>(qw, kw, vw, ow, wsp);

    // K1: shortcut LIF -> Ax (new j-layout)
    dim3 g1(B_, 32);
    lif_x_kernel<<<g1, 256>>>(x, ax);

    // G1: q/k/v GEMMs + fused BN+LIF epilogue -> Aq/Ak/Av spikes (+vh)
    GemmArgs a1;
    a1.Bact = ax;
    a1.W[0] = wsp; a1.W[1] = wsp + 3 * 262144; a1.W[2] = wsp + 6 * 262144;
    a1.g[0] = qg; a1.g[1] = kg; a1.g[2] = vg;
    a1.bb[0] = qb; a1.bb[1] = kb; a1.bb[2] = vb;
    a1.m[0] = qm; a1.m[1] = km; a1.m[2] = vm;
    a1.vv[0] = qv; a1.vv[1] = kvv; a1.vv[2] = vvv;
    a1.Asp[0] = aq; a1.Asp[1] = ak; a1.Asp[2] = av;
    a1.vh = out2;
    a1.kvs = nullptr; a1.out = nullptr; a1.bias = nullptr; a1.xid = nullptr;
    dim3 gg1(J_ / 128, C_ / 128, 3);
    gemm_mma<false><<<gg1, 256, SMEM_DYN>>>(a1);

    // K4: kv reduction + LIF
    dim3 g4(B_, 8);
    kv_lif_kernel<<<g4, 256>>>(ak, av, kvs);

    // G2: out GEMM (B = Aq masked by kvs in-smem) + bias + BN + residual
    GemmArgs a2;
    a2.Bact = aq;
    a2.W[0] = wsp + 9 * 262144; a2.W[1] = a2.W[2] = a2.W[0];
    a2.g[0] = a2.g[1] = a2.g[2] = og;
    a2.bb[0] = a2.bb[1] = a2.bb[2] = obb;
    a2.m[0] = a2.m[1] = a2.m[2] = om;
    a2.vv[0] = a2.vv[1] = a2.vv[2] = ov;
    a2.Asp[0] = a2.Asp[1] = a2.Asp[2] = nullptr;
    a2.vh = nullptr;
    a2.kvs = kvs;
    a2.out = out1;
    a2.bias = ob;
    a2.xid = x;
    dim3 gg2(J_ / 128, C_ / 128, 1);
    gemm_mma<true><<<gg2, 256, SMEM_DYN>>>(a2);
}

// round 15
// speedup vs baseline: 3.2633x; 1.2478x over previous
#include <cuda_runtime.h>
#include <cuda_fp16.h>
#include <stdint.h>

// Problem dims
#define T_ 4
#define B_ 32
#define C_ 512
#define N_ 196            // H*W
#define TB_ 128           // T*B
#define TBCN_ 12845056    // T*B*C*N
#define J_ 25088          // TB*N (GEMM columns), ordered j = (b*196+n)*4 + t

// ---------------- static scratch (allocation-free) ----------------
__device__ __half g_ax[TBCN_];    // x spikes  [j][c]
__device__ __half g_aq[TBCN_];    // q spikes  [j][c]
__device__ __half g_ak[TBCN_];    // k spikes  [j][c]
__device__ __half g_av[TBCN_];    // v spikes  [j][c]
__device__ __half g_wsp[4 * 2 * 262144];  // weight fp16 2-limb splits [mat][s][d*512+c]
__device__ unsigned char g_kvs[TB_ * C_];  // kv spikes [tb][c]

// ================= helpers =================
__device__ __forceinline__ uint32_t smem_u32(const void* p) {
    uint32_t a;
    asm("{ .reg .u64 t; cvta.to.shared.u64 t, %1; cvt.u32.u64 %0, t; }" : "=r"(a) : "l"(p));
    return a;
}
__device__ __forceinline__ void cp16(uint32_t dst, const void* src) {
    asm volatile("cp.async.cg.shared.global [%0], [%1], 16;" :: "r"(dst), "l"(src));
}
#define CP_COMMIT() asm volatile("cp.async.commit_group;" ::: "memory")
#define CP_WAIT1()  asm volatile("cp.async.wait_group 1;" ::: "memory")
#define CP_WAIT0()  asm volatile("cp.async.wait_group 0;" ::: "memory")

__device__ __forceinline__ void ldm_x4(uint32_t addr, uint32_t& r0, uint32_t& r1,
                                       uint32_t& r2, uint32_t& r3) {
    asm volatile("ldmatrix.sync.aligned.m8n8.x4.shared.b16 {%0,%1,%2,%3}, [%4];"
                 : "=r"(r0), "=r"(r1), "=r"(r2), "=r"(r3) : "r"(addr));
}
__device__ __forceinline__ void mma16816(float* c, const uint32_t* a, const uint32_t* b) {
    asm volatile("mma.sync.aligned.m16n8k16.row.col.f32.f16.f16.f32 "
                 "{%0,%1,%2,%3}, {%4,%5,%6,%7}, {%8,%9}, {%0,%1,%2,%3};"
                 : "+f"(c[0]), "+f"(c[1]), "+f"(c[2]), "+f"(c[3])
                 : "r"(a[0]), "r"(a[1]), "r"(a[2]), "r"(a[3]), "r"(b[0]), "r"(b[1]));
}

// smem tile geometry: row stride 40 fp16 (80B) -> ldmatrix conflict-free
#define RS 40
#define B_TILE_B (128 * RS * 2)          // 10240 bytes
#define A_TILE_B (128 * RS * 2)          // per split
#define NSPLIT 2
#define BUF_B (B_TILE_B + NSPLIT * A_TILE_B)  // 30720
#define SMEM_DYN 69632                   // >= 2*BUF_B (61440) and >= 128*133*4 (68096)

// ---------------- K0: weight fp16 2-limb split ----------------
__global__ void split_w_kernel(const float* __restrict__ w0, const float* __restrict__ w1,
                               const float* __restrict__ w2, const float* __restrict__ w3,
                               __half* __restrict__ out) {
    int i = blockIdx.x * 256 + threadIdx.x;  // over 4*262144
    int mat = i >> 18;
    int k = i & 262143;
    const float* W = (mat == 0) ? w0 : (mat == 1) ? w1 : (mat == 2) ? w2 : w3;
    float w = W[k];
    __half f0 = __float2half_rn(w);
    float r = w - __half2float(f0);
    __half f1 = __float2half_rn(r);   // fp16 subnormals cover the residual range
    __half* o = out + (size_t)mat * 2 * 262144;
    o[k] = f0;
    o[262144 + k] = f1;
}

// ---------------- K1: shortcut LIF: x[t][b][c][n] -> Ax fp16 [j][c], j=(b*196+n)*4+t ----
__global__ __launch_bounds__(256) void lif_x_kernel(const float* __restrict__ x,
                                                    __half* __restrict__ Ax) {
    __shared__ float xt[16][197];
    __shared__ float vv[16][197];
    int b = blockIdx.x, c0 = blockIdx.y * 16, tid = threadIdx.x;
    for (int i = tid; i < 16 * 197; i += 256) ((float*)vv)[i] = 0.f;
    __syncthreads();
    const __half one = __float2half_rn(1.0f);
    const __half zero = __float2half_rn(0.0f);
    for (int t = 0; t < T_; t++) {
        for (int i = tid; i < 16 * 196; i += 256) {
            int cc = i / 196, n = i - cc * 196;
            xt[cc][n] = x[(size_t)(((t * B_ + b) * C_) + c0 + cc) * N_ + n];
        }
        __syncthreads();
        for (int i = tid; i < 16 * 196; i += 256) {
            int n = i >> 4, cc = i & 15;
            float v = vv[cc][n];
            v += (xt[cc][n] - v) * 0.5f;
            bool s = (v >= 1.0f);
            int j = (b * 196 + n) * 4 + t;
            Ax[(size_t)j * C_ + c0 + cc] = s ? one : zero;
            vv[cc][n] = s ? 0.f : v;
        }
        __syncthreads();
    }
}

// ---------------- K4: kv = sum_n(k&v), LIF over t -> kvs[tb][c] ----------------
__global__ __launch_bounds__(256) void kv_lif_kernel(const __half* __restrict__ Ak,
                                                     const __half* __restrict__ Av,
                                                     unsigned char* __restrict__ kvs) {
    __shared__ int red[4][4][64];  // [nq][t][c]
    int b = blockIdx.x, c0 = blockIdx.y * 64;
    int cc = threadIdx.x & 63, q = threadIdx.x >> 6;
    const unsigned short* ak = (const unsigned short*)Ak;
    const unsigned short* av = (const unsigned short*)Av;
    int cnt[4] = {0, 0, 0, 0};
    int nbeg = q * 49;
#pragma unroll 7
    for (int n = nbeg; n < nbeg + 49; n++) {
        size_t base = (size_t)((b * 196 + n) * 4) * C_ + c0 + cc;
#pragma unroll
        for (int t = 0; t < 4; t++)
            cnt[t] += ((ak[base + t * C_] & av[base + t * C_]) != 0);
    }
#pragma unroll
    for (int t = 0; t < 4; t++) red[q][t][cc] = cnt[t];
    __syncthreads();
    if (q == 0) {
        float v = 0.f;
#pragma unroll
        for (int t = 0; t < 4; t++) {
            float pre = (float)(red[0][t][cc] + red[1][t][cc] + red[2][t][cc] + red[3][t][cc]);
            v += (pre - v) * 0.5f;
            bool s = (v >= 1.0f);
            kvs[(t * B_ + b) * C_ + c0 + cc] = (unsigned char)s;
            if (s) v = 0.f;
        }
    }
}

// ---------------- HMMA GEMM ----------------
// QKV (!OUT): P = W_z * Ax, BN, then fused 4-step LIF over adjacent t columns;
//             writes fp16 spikes to Asp[z] (+ vh for z==2).
// OUT:        B operand = Aq masked in-smem by kvs; epilogue BN+bias+residual -> out.
struct GemmArgs {
    const __half* Bact;
    const __half* W[3];
    const float* g[3];
    const float* bb[3];
    const float* m[3];
    const float* vv[3];
    __half* Asp[3];            // QKV: spike outputs
    float* vh;                 // QKV z==2
    const unsigned char* kvs;  // OUT
    float* out;                // OUT
    const float* bias;         // OUT
    const float* xid;          // OUT
};

template <bool OUT>
__global__ __launch_bounds__(256) void gemm_mma(GemmArgs ga) {
    extern __shared__ char sm[];
    __shared__ float scs[128];
    __shared__ float shs[128];
    uint32_t sb = smem_u32(sm);
    int tid = threadIdx.x, lane = tid & 31, wid = tid >> 5;
    int wd = wid >> 2, wj = wid & 3;            // warps: 2 (d) x 4 (j)
    int j0 = blockIdx.x * 128, d0 = blockIdx.y * 128, z = blockIdx.z;
    const __half* __restrict__ Wz = ga.W[z];
    const __half* __restrict__ Ba = ga.Bact;

    // BN scale/shift
    if (tid < 128) {
        int d = d0 + tid;
        float sc = ga.g[z][d] / sqrtf(ga.vv[z][d] + 1e-5f);
        float sh = ga.bb[z][d] - ga.m[z][d] * sc;
        if (OUT) sh += ga.bias[d] * sc;
        scs[tid] = sc;
        shs[tid] = sh;
    }

    float acc[4][4][4];
#pragma unroll
    for (int a = 0; a < 4; a++)
#pragma unroll
        for (int b = 0; b < 4; b++)
#pragma unroll
            for (int c = 0; c < 4; c++) acc[a][b][c] = 0.f;

    int brow = tid >> 2, bseg = tid & 3;  // B slots: rows brow, brow+64; 8 cols each

    // OUT: per-thread tb of its two B rows (constant across chunks)
    int tb_r[2];
    if (OUT) {
#pragma unroll
        for (int i = 0; i < 2; i++) {
            int j = j0 + brow + i * 64;
            int t = j & 3, g = j >> 2, b = g / 196;
            tb_r[i] = t * B_ + b;
        }
    }

    auto load_chunk = [&](int buf, int it) {
        int c0 = it * 32;
        uint32_t base = sb + buf * BUF_B;
#pragma unroll
        for (int i = 0; i < 2; i++) {
            int row = brow + i * 64;
            cp16(base + row * (RS * 2) + bseg * 16,
                 Ba + (size_t)(j0 + row) * C_ + c0 + bseg * 8);
        }
#pragma unroll
        for (int i = 0; i < 2 * NSPLIT; i++) {
            int e = tid + i * 256;
            int s = e >> 9;
            int row = (e >> 2) & 127;
            int seg = e & 3;
            cp16(base + B_TILE_B + s * A_TILE_B + row * (RS * 2) + seg * 16,
                 Wz + (size_t)s * 262144 + (size_t)(d0 + row) * C_ + c0 + seg * 8);
        }
    };

    // ldmatrix address patterns
    int sub = lane >> 3, l7 = lane & 7;
    int a_r = (sub & 1) * 8 + l7, a_c2 = (sub >> 1) * 8;
    int b_r = (sub >> 1) * 8 + l7, b_c2 = (sub & 1) * 8;

    load_chunk(0, 0);
    CP_COMMIT();

    for (int it = 0; it < 16; it++) {
        if (it < 15) {
            load_chunk((it + 1) & 1, it + 1);
            CP_COMMIT();
            CP_WAIT1();
        } else {
            CP_WAIT0();
        }

        // OUT: mask own B slots with kvs (this thread's own cp.async data, now complete)
        if (OUT) {
            int c0 = it * 32;
#pragma unroll
            for (int i = 0; i < 2; i++) {
                int row = brow + i * 64;
                const unsigned char* kp = ga.kvs + tb_r[i] * C_ + c0 + bseg * 8;
                uint32_t k0 = *(const uint32_t*)kp;
                uint32_t k1 = *(const uint32_t*)(kp + 4);
                uint4* sp = (uint4*)(sm + (it & 1) * BUF_B + row * (RS * 2) + bseg * 16);
                uint4 w = *sp;
                w.x &= ((k0 & 0xFFu) ? 0xFFFFu : 0u) | ((k0 & 0xFF00u) ? 0xFFFF0000u : 0u);
                w.y &= ((k0 & 0xFF0000u) ? 0xFFFFu : 0u) | ((k0 & 0xFF000000u) ? 0xFFFF0000u : 0u);
                w.z &= ((k1 & 0xFFu) ? 0xFFFFu : 0u) | ((k1 & 0xFF00u) ? 0xFFFF0000u : 0u);
                w.w &= ((k1 & 0xFF0000u) ? 0xFFFFu : 0u) | ((k1 & 0xFF000000u) ? 0xFFFF0000u : 0u);
                *sp = w;
            }
        }
        __syncthreads();

        uint32_t base = sb + (it & 1) * BUF_B;
        uint32_t bB = base;
        uint32_t bA = base + B_TILE_B;

        uint32_t bf[2][4][2];
#pragma unroll
        for (int k16 = 0; k16 < 2; k16++)
#pragma unroll
            for (int np = 0; np < 2; np++) {
                int row = wj * 32 + np * 16 + b_r;
                int col = k16 * 16 + b_c2;
                uint32_t addr = bB + row * (RS * 2) + col * 2;
                ldm_x4(addr, bf[k16][np * 2][0], bf[k16][np * 2][1],
                       bf[k16][np * 2 + 1][0], bf[k16][np * 2 + 1][1]);
            }

#pragma unroll
        for (int s = 0; s < NSPLIT; s++) {
#pragma unroll
            for (int k16 = 0; k16 < 2; k16++) {
#pragma unroll
                for (int mi = 0; mi < 4; mi++) {
                    uint32_t af[4];
                    int row = wd * 64 + mi * 16 + a_r;
                    int col = k16 * 16 + a_c2;
                    uint32_t addr = bA + s * A_TILE_B + row * (RS * 2) + col * 2;
                    ldm_x4(addr, af[0], af[1], af[2], af[3]);
#pragma unroll
                    for (int ni = 0; ni < 4; ni++)
                        mma16816(acc[mi][ni], af, bf[k16][ni]);
                }
            }
        }
        __syncthreads();
    }

    // ---------------- epilogue ----------------
    int r = lane >> 2, cq = (lane & 3) * 2;
    if (OUT) {
        const float* xid = ga.xid;
        float* o = ga.out;
#pragma unroll
        for (int mi = 0; mi < 4; mi++) {
            int dl0 = wd * 64 + mi * 16 + r;
#pragma unroll
            for (int ni = 0; ni < 4; ni++) {
                int jj = j0 + wj * 32 + ni * 8 + cq;
                float v[4];
                v[0] = acc[mi][ni][0] * scs[dl0] + shs[dl0];
                v[1] = acc[mi][ni][1] * scs[dl0] + shs[dl0];
                v[2] = acc[mi][ni][2] * scs[dl0 + 8] + shs[dl0 + 8];
                v[3] = acc[mi][ni][3] * scs[dl0 + 8] + shs[dl0 + 8];
#pragma unroll
                for (int e = 0; e < 4; e++) {
                    int dd = d0 + dl0 + (e >> 1) * 8;
                    int j = jj + (e & 1);
                    int t = j & 3, g = j >> 2;
                    int b = g / 196, n = g - b * 196;
                    size_t gi = (size_t)((t * B_ + b) * C_ + dd) * N_ + n;
                    o[gi] = v[e] + xid[gi];
                }
            }
        }
    } else {
        // stage BN'd pre-acts to smem [d][j_local], stride 133 (odd -> LIF reads
        // conflict-free). Scalar stores only (odd stride => float2 would misalign).
        float* S = (float*)sm;
#pragma unroll
        for (int mi = 0; mi < 4; mi++) {
            int dl0 = wd * 64 + mi * 16 + r;
#pragma unroll
            for (int ni = 0; ni < 4; ni++) {
                int jj = wj * 32 + ni * 8 + cq;
                S[dl0 * 133 + jj] = acc[mi][ni][0] * scs[dl0] + shs[dl0];
                S[dl0 * 133 + jj + 1] = acc[mi][ni][1] * scs[dl0] + shs[dl0];
                S[(dl0 + 8) * 133 + jj] = acc[mi][ni][2] * scs[dl0 + 8] + shs[dl0 + 8];
                S[(dl0 + 8) * 133 + jj + 1] = acc[mi][ni][3] * scs[dl0 + 8] + shs[dl0 + 8];
            }
        }
        __syncthreads();
        const __half one = __float2half_rn(1.0f);
        const __half zero = __float2half_rn(0.0f);
        __half* A = ga.Asp[z];
#pragma unroll 1
        for (int p = 0; p < 16; p++) {
            int sid = p * 256 + tid;
            int d = sid & 127, gl = sid >> 7;  // gl in 0..31
            int jbase = j0 + gl * 4;
            int g = jbase >> 2;
            int b = g / 196, n = g - b * 196;
            int c = d0 + d;
            float v = 0.f;
#pragma unroll
            for (int t = 0; t < 4; t++) {
                float pre = S[d * 133 + gl * 4 + t];
                v += (pre - v) * 0.5f;
                bool s = (v >= 1.0f);
                A[(size_t)(jbase + t) * C_ + c] = s ? one : zero;
                if (z == 2) {
                    ga.vh[(size_t)(t * B_ + b) * 100352 + (c >> 6) * 12544 + n * 64 + (c & 63)] =
                        s ? 1.0f : 0.0f;
                }
                if (s) v = 0.f;
            }
        }
    }
}

// ---------------- host launch ----------------
extern "C" void kernel_launch(void* const* d_in, const int* in_sizes, int n_in,
                              void* d_out, int out_size) {
    const float *x, *qw, *kw, *vw, *ow, *ob;
    const float *qg, *qb, *qm, *qv, *kg, *kb, *km, *kvv, *vg, *vb, *vm, *vvv, *og, *obb, *om, *ov;
    if (n_in >= 5 && in_sizes[2] == 262144) {
        x = (const float*)d_in[0];
        qw = (const float*)d_in[1]; kw = (const float*)d_in[2];
        vw = (const float*)d_in[3]; ow = (const float*)d_in[4];
        ob = (const float*)d_in[5];
        qg = (const float*)d_in[6];  qb = (const float*)d_in[7];  qm = (const float*)d_in[8];  qv = (const float*)d_in[9];
        kg = (const float*)d_in[10]; kb = (const float*)d_in[11]; km = (const float*)d_in[12]; kvv = (const float*)d_in[13];
        vg = (const float*)d_in[14]; vb = (const float*)d_in[15]; vm = (const float*)d_in[16]; vvv = (const float*)d_in[17];
        og = (const float*)d_in[18]; obb = (const float*)d_in[19]; om = (const float*)d_in[20]; ov = (const float*)d_in[21];
    } else {
        x = (const float*)d_in[0];
        qw = (const float*)d_in[1];
        qg = (const float*)d_in[2];  qb = (const float*)d_in[3];  qm = (const float*)d_in[4];  qv = (const float*)d_in[5];
        kw = (const float*)d_in[6];
        kg = (const float*)d_in[7];  kb = (const float*)d_in[8];  km = (const float*)d_in[9];  kvv = (const float*)d_in[10];
        vw = (const float*)d_in[11];
        vg = (const float*)d_in[12]; vb = (const float*)d_in[13]; vm = (const float*)d_in[14]; vvv = (const float*)d_in[15];
        ow = (const float*)d_in[16]; ob = (const float*)d_in[17];
        og = (const float*)d_in[18]; obb = (const float*)d_in[19]; om = (const float*)d_in[20]; ov = (const float*)d_in[21];
    }

    float* out1 = (float*)d_out;
    float* out2 = (float*)d_out + TBCN_;

    __half *ax, *aq, *ak, *av, *wsp;
    unsigned char* kvs;
    cudaGetSymbolAddress((void**)&ax, g_ax);
    cudaGetSymbolAddress((void**)&aq, g_aq);
    cudaGetSymbolAddress((void**)&ak, g_ak);
    cudaGetSymbolAddress((void**)&av, g_av);
    cudaGetSymbolAddress((void**)&wsp, g_wsp);
    cudaGetSymbolAddress((void**)&kvs, g_kvs);

    cudaFuncSetAttribute(gemm_mma<false>, cudaFuncAttributeMaxDynamicSharedMemorySize, SMEM_DYN);
    cudaFuncSetAttribute(gemm_mma<true>, cudaFuncAttributeMaxDynamicSharedMemorySize, SMEM_DYN);

    // K0: weight fp16 2-limb splits
    split_w_kernel<<<4096, 256>>>(qw, kw, vw, ow, wsp);

    // K1: shortcut LIF -> Ax
    dim3 g1(B_, 32);
    lif_x_kernel<<<g1, 256>>>(x, ax);

    // G1: q/k/v GEMMs + fused BN+LIF epilogue -> Aq/Ak/Av spikes (+vh)
    GemmArgs a1;
    a1.Bact = ax;
    a1.W[0] = wsp; a1.W[1] = wsp + 2 * 262144; a1.W[2] = wsp + 4 * 262144;
    a1.g[0] = qg; a1.g[1] = kg; a1.g[2] = vg;
    a1.bb[0] = qb; a1.bb[1] = kb; a1.bb[2] = vb;
    a1.m[0] = qm; a1.m[1] = km; a1.m[2] = vm;
    a1.vv[0] = qv; a1.vv[1] = kvv; a1.vv[2] = vvv;
    a1.Asp[0] = aq; a1.Asp[1] = ak; a1.Asp[2] = av;
    a1.vh = out2;
    a1.kvs = nullptr; a1.out = nullptr; a1.bias = nullptr; a1.xid = nullptr;
    dim3 gg1(J_ / 128, C_ / 128, 3);
    gemm_mma<false><<<gg1, 256, SMEM_DYN>>>(a1);

    // K4: kv reduction + LIF
    dim3 g4(B_, 8);
    kv_lif_kernel<<<g4, 256>>>(ak, av, kvs);

    // G2: out GEMM (B = Aq masked by kvs in-smem) + bias + BN + residual
    GemmArgs a2;
    a2.Bact = aq;
    a2.W[0] = wsp + 6 * 262144; a2.W[1] = a2.W[2] = a2.W[0];
    a2.g[0] = a2.g[1] = a2.g[2] = og;
    a2.bb[0] = a2.bb[1] = a2.bb[2] = obb;
    a2.m[0] = a2.m[1] = a2.m[2] = om;
    a2.vv[0] = a2.vv[1] = a2.vv[2] = ov;
    a2.Asp[0] = a2.Asp[1] = a2.Asp[2] = nullptr;
    a2.vh = nullptr;
    a2.kvs = kvs;
    a2.out = out1;
    a2.bias = ob;
    a2.xid = x;
    dim3 gg2(J_ / 128, C_ / 128, 1);
    gemm_mma<true><<<gg2, 256, SMEM_DYN>>>(a2);
}